// round 13
// baseline (speedup 1.0000x reference)
#include <cuda_runtime.h>
#include <cuda_bf16.h>
#include <math.h>
#include <stdint.h>

// Problem constants
#define B_    64
#define PANO_ 36
#define OBJ_  36
#define CFG_  16
#define LM_   8
#define IMG_  32
#define D_    300
#define H_    512
#define EMB_  64
#define ANG_  128
#define FEAT_ 2176
#define TOPN_ 3
#define M_    128
#define EPS_  1e-8f

// Output layout (flattened tuple): h_1 | c_1 | logit | h_tilde | ctx_attn
#define OFF_H1   0
#define OFF_C1   32768
#define OFF_LOG  65536
#define OFF_HT   67584
#define OFF_CA   100352

// ---------------- scratch ----------------
__device__ __align__(256) float g_x[B_*3140];       // [action_emb(64) | attn_feat(3076)]
__device__ __align__(256) float g_qfeat[B_*3076];
__device__ __align__(256) float g_cat[B_*1024];
__device__ __align__(256) float g_q2[B_*3097];
__device__ __align__(256) float g_part[800000];     // generic split-K partials (qfeat / ih / q2)
__device__ __align__(256) float g_parthh[4*64*2048];
__device__ __align__(256) float g_part2[8*64*512];  // att_out partials
__device__ __align__(256) float g_pano_sim[B_*PANO_*900];
__device__ float g_a[B_*PANO_];
__device__ int   g_top1[B_*3];
__device__ float g_nb1[B_*3];
__device__ int   g_top2[B_*3];
__device__ float g_nb2[B_*3];
__device__ float g_relmask[B_*3];
__device__ float g_landrel[B_*18];

// ---------------- helpers ----------------
__device__ __forceinline__ float wred(float v) {
    #pragma unroll
    for (int o = 16; o; o >>= 1) v += __shfl_down_sync(0xffffffffu, v, o);
    return v;
}
__device__ __forceinline__ float block_reduce(float v, float* sbuf) {
    int lane = threadIdx.x & 31, w = threadIdx.x >> 5;
    v = wred(v);
    if (lane == 0) sbuf[w] = v;
    __syncthreads();
    int nw = blockDim.x >> 5;
    v = (threadIdx.x < nw) ? sbuf[threadIdx.x] : 0.f;
    if (w == 0) v = wred(v);
    return v;
}
__device__ __forceinline__ float sigmoidf_(float x) { return 1.f / (1.f + expf(-x)); }

// ---------------- FFMA split-K GEMM body (proven, float4 loads) ----------------
__device__ void gemm64_body(const float* __restrict__ A, int lda,
                            const float* __restrict__ W, int N, int K,
                            int kChunk, float* __restrict__ part,
                            int jbi, int ky) {
    __shared__ float sA[16][64];
    __shared__ float sW[16][64];
    int jb = jbi * 64;
    int k0 = ky * kChunk;
    int kEnd = min(K, k0 + kChunk);
    int tid = threadIdx.x;                 // 128 threads
    int tj = tid & 15, tb = tid >> 4;
    float acc[8][4];
    #pragma unroll
    for (int r = 0; r < 8; r++)
        #pragma unroll
        for (int c = 0; c < 4; c++) acc[r][c] = 0.f;
    int la_b = tid >> 1, la_k = (tid & 1) * 8;
    int lw_k = tid >> 3, lw_j = (tid & 7) * 8;
    bool wAligned = ((N & 3) == 0);
    for (int k = k0; k < kEnd; k += 16) {
        int kw = kEnd - k;
        if (la_k + 8 <= kw) {
            const float* ap = A + (size_t)la_b * lda + k + la_k;
            float4 v0 = *(const float4*)ap;
            float4 v1 = *(const float4*)(ap + 4);
            sA[la_k+0][la_b] = v0.x; sA[la_k+1][la_b] = v0.y;
            sA[la_k+2][la_b] = v0.z; sA[la_k+3][la_b] = v0.w;
            sA[la_k+4][la_b] = v1.x; sA[la_k+5][la_b] = v1.y;
            sA[la_k+6][la_b] = v1.z; sA[la_k+7][la_b] = v1.w;
        } else {
            #pragma unroll
            for (int e = 0; e < 8; e++) {
                int kk = la_k + e;
                sA[kk][la_b] = (kk < kw) ? A[(size_t)la_b * lda + k + kk] : 0.f;
            }
        }
        int kg = k + lw_k;
        int jg0 = jb + lw_j;
        if (lw_k < kw && wAligned && jg0 + 8 <= N) {
            const float* wp = W + (size_t)kg * N + jg0;
            float4 w0 = *(const float4*)wp;
            float4 w1 = *(const float4*)(wp + 4);
            sW[lw_k][lw_j+0] = w0.x; sW[lw_k][lw_j+1] = w0.y;
            sW[lw_k][lw_j+2] = w0.z; sW[lw_k][lw_j+3] = w0.w;
            sW[lw_k][lw_j+4] = w1.x; sW[lw_k][lw_j+5] = w1.y;
            sW[lw_k][lw_j+6] = w1.z; sW[lw_k][lw_j+7] = w1.w;
        } else {
            #pragma unroll
            for (int e = 0; e < 8; e++) {
                int jg = jg0 + e;
                sW[lw_k][lw_j+e] = (lw_k < kw && jg < N) ? W[(size_t)kg * N + jg] : 0.f;
            }
        }
        __syncthreads();
        #pragma unroll
        for (int kk = 0; kk < 16; kk++) {
            float av[8], wv[4];
            #pragma unroll
            for (int r = 0; r < 8; r++) av[r] = sA[kk][tb * 8 + r];
            #pragma unroll
            for (int c = 0; c < 4; c++) wv[c] = sW[kk][tj * 4 + c];
            #pragma unroll
            for (int r = 0; r < 8; r++)
                #pragma unroll
                for (int c = 0; c < 4; c++) acc[r][c] += av[r] * wv[c];
        }
        __syncthreads();
    }
    float* pp = part + (size_t)ky * 64 * N;
    #pragma unroll
    for (int r = 0; r < 8; r++) {
        int b = tb * 8 + r;
        #pragma unroll
        for (int c = 0; c < 4; c++) {
            int j = jb + tj * 4 + c;
            if (j < N) pp[(size_t)b * N + j] = acc[r][c];
        }
    }
}

__global__ void __launch_bounds__(128) k_gemm64(
        const float* __restrict__ A, int lda, const float* __restrict__ W,
        int N, int K, int kChunk, float* __restrict__ part) {
    gemm64_body(A, lda, W, N, K, kChunk, part, blockIdx.x, blockIdx.y);
}

__global__ void __launch_bounds__(128) k_gemm_pair64(
        const float* __restrict__ A0, int lda0, const float* __restrict__ W0,
        int N0, int K0, int kc0, float* __restrict__ p0, int njb0, int nb0,
        const float* __restrict__ A1, int lda1, const float* __restrict__ W1,
        int N1, int K1, int kc1, float* __restrict__ p1, int njb1) {
    int bid = blockIdx.x;
    if (bid < nb0) gemm64_body(A0, lda0, W0, N0, K0, kc0, p0, bid % njb0, bid / njb0);
    else {
        bid -= nb0;
        gemm64_body(A1, lda1, W1, N1, K1, kc1, p1, bid % njb1, bid / njb1);
    }
}

__global__ void k_reduce(const float* __restrict__ part, int S, int N,
                         float* __restrict__ C) {
    int idx = blockIdx.x * 256 + threadIdx.x;
    int MN = 64 * N;
    if (idx >= MN) return;
    float v = 0.f;
    for (int s = 0; s < S; s++) v += part[(size_t)s * MN + idx];
    C[idx] = v;
}

// ---------------- top-k body ----------------
__device__ void topk_body(int b,
                          const float* __restrict__ score,
                          const float* __restrict__ lmask,
                          const float* __restrict__ land,
                          const float* __restrict__ relmask_in,
                          const float* __restrict__ landrel_in,
                          int which) {
    __shared__ float sv[128];
    __shared__ int sel[3];
    int tid = threadIdx.x;
    if (tid < 128) sv[tid] = score[b * 16 + (tid >> 3)] * lmask[b * 128 + tid];
    __syncthreads();
    int* top = which ? g_top2 : g_top1;
    float* nbout = which ? g_nb2 : g_nb1;
    if (tid < 32) {
        for (int r = 0; r < 3; r++) {
            float bv = -INFINITY; int bi = 128;
            for (int m = tid; m < 128; m += 32) {
                float v = sv[m];
                if (v > bv || (v == bv && m < bi)) { bv = v; bi = m; }
            }
            #pragma unroll
            for (int off = 16; off; off >>= 1) {
                float ov = __shfl_down_sync(0xffffffffu, bv, off);
                int   oi = __shfl_down_sync(0xffffffffu, bi, off);
                if (ov > bv || (ov == bv && oi < bi)) { bv = ov; bi = oi; }
            }
            if (tid == 0) { sel[r] = bi; top[b * 3 + r] = bi; sv[bi] = -INFINITY; }
            __syncwarp();
        }
    }
    __syncthreads();
    int w = tid >> 5, lane = tid & 31;
    if (w < 3) {
        int m = sel[w];
        const float* p = land + ((size_t)b * 128 + m) * D_;
        float s = 0.f;
        for (int d = lane; d < D_; d += 32) { float v = p[d]; s += v * v; }
        s = wred(s);
        if (lane == 0) nbout[b * 3 + w] = sqrtf(s);
    }
    if (relmask_in && tid < 3)
        g_relmask[b * 3 + tid] = relmask_in[b * 128 + sel[tid]];
    if (landrel_in && tid < 18) {
        int t = tid / 6, r2 = tid % 6;
        g_landrel[b * 18 + tid] = landrel_in[((size_t)b * 128 + sel[t]) * 6 + r2];
    }
}

// ---------------- merged: action embedding (16 blocks) + topk1 (64 blocks) ----------------
__global__ void __launch_bounds__(256) k_misc1(
        const float* __restrict__ action, const float* __restrict__ embW,
        const float* __restrict__ embB,
        const float* __restrict__ s_0, const float* __restrict__ lmask,
        const float* __restrict__ land) {
    if (blockIdx.x < 16) {
        int idx = blockIdx.x * 256 + threadIdx.x;
        if (idx >= B_ * EMB_) return;
        int b = idx >> 6, e = idx & 63;
        float acc = embB[e];
        const float* a = action + b * ANG_;
        #pragma unroll 4
        for (int k = 0; k < ANG_; k++) acc += a[k] * embW[k * EMB_ + e];
        g_x[(size_t)b * 3140 + e] = tanhf(acc);
    } else {
        topk_body(blockIdx.x - 16, s_0, lmask, land, nullptr, nullptr, 0);
    }
}

// ---------------- merged: att_out GEMM (64 blocks, splitK) + topk2 (64 blocks) ----------------
__global__ void __launch_bounds__(128) k_attout_topk(
        const float* __restrict__ A, const float* __restrict__ W,
        const float* __restrict__ ctx_attn_out, const float* __restrict__ lmask,
        const float* __restrict__ land,
        const float* __restrict__ relmask_in, const float* __restrict__ landrel_in) {
    if (blockIdx.x < 64) {
        gemm64_body(A, 1024, W, 512, 1024, 128, g_part2, blockIdx.x & 7, blockIdx.x >> 3);
    } else {
        topk_body(blockIdx.x - 64, ctx_attn_out, lmask, land, relmask_in, landrel_in, 1);
    }
}

// ---------------- fused object retrieval + dot-with-query ----------------
// Landmark vectors register-cached per lane (kills LDS in the hot loop).
__global__ void __launch_bounds__(256) k_objret(
        const float* __restrict__ obj, int I,
        const float* __restrict__ land,
        const float* __restrict__ extra,      // feature or cand_feat [B,I,FEAT]
        const float* __restrict__ qbase,      // g_qfeat or g_q2
        const float* __restrict__ crel,       // [B,IMG,6] (which=1 only)
        float* __restrict__ aout, int which) {
    int bi = blockIdx.x;
    int b = bi / I;
    __shared__ float4 sl4[3][76];
    __shared__ float snb[3];
    __shared__ float ssim[OBJ_][3];
    __shared__ int sbest[3];
    __shared__ float sred[8];
    int tid = threadIdx.x;
    const int* top = which ? g_top2 : g_top1;
    const float* nb = which ? g_nb2 : g_nb1;
    if (tid < 228) {
        int t = tid / 76, i = tid % 76;
        if (i < 75)
            sl4[t][i] = ((const float4*)(land + ((size_t)b * 128 + top[b * 3 + t]) * D_))[i];
        else {
            float4 z; z.x = z.y = z.z = z.w = 0.f; sl4[t][i] = z;
        }
    }
    if (tid < 3) snb[tid] = nb[b * 3 + tid];
    __syncthreads();

    int w = tid >> 5, lane = tid & 31;
    // register-cache the landmark slots this lane will use (slot s -> i = lane + 32*s)
    float4 la[3][3];
    #pragma unroll
    for (int s = 0; s < 3; s++) {
        int i = lane + 32 * s;
        bool v = (i < 75);
        int ii = v ? i : 75;            // padded zero slot
        #pragma unroll
        for (int t = 0; t < 3; t++) la[t][s] = sl4[t][ii];
    }

    const float* ob = obj + (size_t)bi * OBJ_ * D_;
    for (int o = w; o < OBJ_; o += 8) {
        const float4* po4 = (const float4*)(ob + o * D_);
        float d0 = 0.f, d1 = 0.f, d2 = 0.f, nr = 0.f;
        #pragma unroll
        for (int s = 0; s < 3; s++) {
            int i = lane + 32 * s;
            if (i < 75) {
                float4 v = po4[i];
                d0 += v.x*la[0][s].x + v.y*la[0][s].y + v.z*la[0][s].z + v.w*la[0][s].w;
                d1 += v.x*la[1][s].x + v.y*la[1][s].y + v.z*la[1][s].z + v.w*la[1][s].w;
                d2 += v.x*la[2][s].x + v.y*la[2][s].y + v.z*la[2][s].z + v.w*la[2][s].w;
                nr += v.x*v.x + v.y*v.y + v.z*v.z + v.w*v.w;
            }
        }
        #pragma unroll
        for (int off = 16; off; off >>= 1) {
            d0 += __shfl_down_sync(0xffffffffu, d0, off);
            d1 += __shfl_down_sync(0xffffffffu, d1, off);
            d2 += __shfl_down_sync(0xffffffffu, d2, off);
            nr += __shfl_down_sync(0xffffffffu, nr, off);
        }
        if (lane == 0) {
            float na = sqrtf(nr);
            ssim[o][0] = d0 / fmaxf(na * snb[0], EPS_);
            ssim[o][1] = d1 / fmaxf(na * snb[1], EPS_);
            ssim[o][2] = d2 / fmaxf(na * snb[2], EPS_);
        }
    }
    __syncthreads();
    if (tid < 3) {
        float bv = -INFINITY; int bo = 0;
        for (int o = 0; o < OBJ_; o++) { float v = ssim[o][tid]; if (v > bv) { bv = v; bo = o; } }
        sbest[tid] = bo;
    }
    __syncthreads();

    int qStride = which ? 3097 : 3076;
    int tStride = which ? 307  : 300;
    const float* q = qbase + (size_t)b * qStride;
    float accq = 0.f;
    const float4* f4 = (const float4*)(extra + (size_t)bi * FEAT_);
    #pragma unroll 2
    for (int i = tid; i < FEAT_/4; i += 256) {
        float4 v = f4[i];
        int d = i * 4;
        accq += v.x*q[d] + v.y*q[d+1] + v.z*q[d+2] + v.w*q[d+3];
    }
    if (tid < 225) {
        int t = tid / 75, i = tid % 75, d = i * 4;
        float4 v = ((const float4*)(ob + sbest[t] * D_))[i];
        if (!which) ((float4*)(g_pano_sim + (size_t)bi * 900 + t * 300))[i] = v;
        const float* qq = q + FEAT_ + t * tStride + d;
        accq += v.x*qq[0] + v.y*qq[1] + v.z*qq[2] + v.w*qq[3];
    }
    if (which && tid < 21) {
        int t = tid / 7, r = tid % 7;
        const float* cr = crel + (size_t)bi * 6;
        if (r < 6) {
            accq += cr[r] * g_relmask[b * 3 + t] * q[FEAT_ + t * 307 + 300 + r];
        } else {
            float dot = 0.f;
            #pragma unroll
            for (int rr = 0; rr < 6; rr++) dot += cr[rr] * g_landrel[b * 18 + t * 6 + rr];
            accq += dot * q[FEAT_ + t * 307 + 306];
        }
    }
    accq = block_reduce(accq, sred);
    if (tid == 0) aout[bi] = accq;
}

// ---------------- attention-weighted feature (softmax inline, float4) ----------------
__global__ void k_attn_feat(const float* __restrict__ feature) {
    int b = blockIdx.y;
    __shared__ float sp[PANO_];
    __shared__ float sms[2];
    if (threadIdx.x < PANO_) sp[threadIdx.x] = g_a[b * PANO_ + threadIdx.x];
    __syncthreads();
    if (threadIdx.x == 0) {
        float m = -INFINITY;
        for (int i = 0; i < PANO_; i++) m = fmaxf(m, sp[i]);
        float su = 0.f;
        for (int i = 0; i < PANO_; i++) su += expf(sp[i] - m);
        sms[0] = m; sms[1] = su;
    }
    __syncthreads();
    if (threadIdx.x < PANO_)
        sp[threadIdx.x] = expf(sp[threadIdx.x] - sms[0]) / sms[1];
    __syncthreads();
    int i = blockIdx.x * 256 + threadIdx.x;   // float4 index over 3076/4 = 769
    if (i >= 769) return;
    int d = i * 4;
    float ax = 0.f, ay = 0.f, az = 0.f, aw = 0.f;
    if (d < FEAT_) {
        const float4* f = (const float4*)(feature + (size_t)b * PANO_ * FEAT_) + i;
        #pragma unroll 4
        for (int s = 0; s < PANO_; s++) {
            float4 v = f[(size_t)s * (FEAT_/4)];
            float p = sp[s];
            ax += p*v.x; ay += p*v.y; az += p*v.z; aw += p*v.w;
        }
    } else {
        const float4* f = (const float4*)(g_pano_sim + (size_t)b * PANO_ * 900 + (d - FEAT_));
        #pragma unroll 4
        for (int s = 0; s < PANO_; s++) {
            float4 v = f[(size_t)s * 225];
            float p = sp[s];
            ax += p*v.x; ay += p*v.y; az += p*v.z; aw += p*v.w;
        }
    }
    float4 o; o.x = ax; o.y = ay; o.z = az; o.w = aw;
    *(float4*)(g_x + (size_t)b * 3140 + 64 + d) = o;
}

// ---------------- LSTM (sums ih(5) + hh(4) partials + bias) ----------------
__global__ void k_lstm(const float* __restrict__ c0,
                       const float* __restrict__ bias,
                       float* __restrict__ out) {
    int idx = blockIdx.x * 256 + threadIdx.x;
    if (idx >= B_ * H_) return;
    int b = idx >> 9, j = idx & 511;
    float g4[4];
    #pragma unroll
    for (int qg = 0; qg < 4; qg++) {
        int col = qg * 512 + j;
        float v = bias[col];
        #pragma unroll
        for (int s = 0; s < 5; s++)
            v += g_part[(size_t)s * 64 * 2048 + (size_t)b * 2048 + col];
        #pragma unroll
        for (int s = 0; s < 4; s++)
            v += g_parthh[(size_t)s * 64 * 2048 + (size_t)b * 2048 + col];
        g4[qg] = v;
    }
    float ig = sigmoidf_(g4[0]);
    float fg = sigmoidf_(g4[1]);
    float gg = tanhf(g4[2]);
    float og = sigmoidf_(g4[3]);
    float c1 = fg * c0[idx] + ig * gg;
    float h1 = og * tanhf(c1);
    out[OFF_H1 + idx] = h1;
    out[OFF_C1 + idx] = c1;
}

// ---------------- ctx attention (qa = h1 @ att_in_W computed inline) ----------------
__global__ void __launch_bounds__(512) k_ctx_attn(
        const float* __restrict__ ctx,
        const float* __restrict__ attW,        // [512,512]
        const unsigned char* __restrict__ cmask,
        float* __restrict__ out) {
    int b = blockIdx.x;
    int tid = threadIdx.x; // 512
    __shared__ float sh1[H_], sqa[H_], slg[CFG_], sattn[CFG_];
    float h1v = out[OFF_H1 + b * H_ + tid];
    sh1[tid] = h1v;
    __syncthreads();
    // qa[tid] = sum_k h1[k] * W[k,tid]   (W streamed, L2-resident across 64 blocks)
    {
        float acc = 0.f;
        const float* wp = attW + tid;
        #pragma unroll 8
        for (int k = 0; k < H_; k++)
            acc += sh1[k] * wp[(size_t)k * H_];
        sqa[tid] = acc;
    }
    __syncthreads();
    int w = tid >> 5, lane = tid & 31;
    const float* cb = ctx + (size_t)b * CFG_ * H_;
    {
        float acc = 0.f;
        const float* cw = cb + w * H_;
        for (int d = lane; d < H_; d += 32) acc += cw[d] * sqa[d];
        acc = wred(acc);
        if (lane == 0) slg[w] = cmask[b * CFG_ + w] ? -INFINITY : acc;
    }
    __syncthreads();
    if (tid == 0) {
        float m = -INFINITY;
        for (int s = 0; s < CFG_; s++) m = fmaxf(m, slg[s]);
        float su = 0.f;
        for (int s = 0; s < CFG_; s++) { float e = expf(slg[s] - m); sattn[s] = e; su += e; }
        float inv = 1.f / su;
        for (int s = 0; s < CFG_; s++) { sattn[s] *= inv; out[OFF_CA + b * CFG_ + s] = sattn[s]; }
    }
    __syncthreads();
    float acc = 0.f;
    #pragma unroll
    for (int s = 0; s < CFG_; s++) acc += sattn[s] * cb[(size_t)s * H_ + tid];
    g_cat[b * 1024 + tid] = acc;
    g_cat[b * 1024 + 512 + tid] = h1v;
}

// ---------------- h_tilde = tanh(sum of 8 att_out partials) ----------------
__global__ void k_tanh_ht(float* __restrict__ out) {
    int idx = blockIdx.x * 256 + threadIdx.x;
    if (idx >= B_ * H_) return;
    float v = 0.f;
    #pragma unroll
    for (int s = 0; s < 8; s++) v += g_part2[(size_t)s * 64 * 512 + idx];
    out[OFF_HT + idx] = tanhf(v);
}

// ---------------- host launcher ----------------
extern "C" void kernel_launch(void* const* d_in, const int* in_sizes, int n_in,
                              void* d_out, int out_size) {
    const float* action    = (const float*)d_in[0];
    const float* feature   = (const float*)d_in[1];
    const float* cand_feat = (const float*)d_in[2];
    const float* prev_h1   = (const float*)d_in[3];
    const float* c_0       = (const float*)d_in[4];
    const float* ctx       = (const float*)d_in[5];
    const float* s_0       = (const float*)d_in[6];
    const float* land      = (const float*)d_in[7];
    const float* cand_obj  = (const float*)d_in[8];
    const float* lmask     = (const float*)d_in[9];
    const float* landrel   = (const float*)d_in[10];
    const float* relmask   = (const float*)d_in[11];
    const float* crel      = (const float*)d_in[12];
    const float* pano_obj  = (const float*)d_in[13];
    const float* embW      = (const float*)d_in[14];
    const float* embB      = (const float*)d_in[15];
    const float* W_ih      = (const float*)d_in[16];
    const float* W_hh      = (const float*)d_in[17];
    const float* b_lstm    = (const float*)d_in[18];
    const float* feat_in_W = (const float*)d_in[19];
    const float* att_in_W  = (const float*)d_in[20];
    const float* att_out_W = (const float*)d_in[21];
    const float* cand_in_W = (const float*)d_in[22];
    const unsigned char* cmask = (const unsigned char*)d_in[23];
    float* out = (float*)d_out;

    float *p_x, *p_qfeat, *p_q2, *p_part, *p_a, *p_cat;
    cudaGetSymbolAddress((void**)&p_x,      g_x);
    cudaGetSymbolAddress((void**)&p_qfeat,  g_qfeat);
    cudaGetSymbolAddress((void**)&p_q2,     g_q2);
    cudaGetSymbolAddress((void**)&p_part,   g_part);
    cudaGetSymbolAddress((void**)&p_a,      g_a);
    cudaGetSymbolAddress((void**)&p_cat,    g_cat);
    float* p_parthh; cudaGetSymbolAddress((void**)&p_parthh, g_parthh);

    // 1) action embedding + topk1
    k_misc1<<<80, 256>>>(action, embW, embB, s_0, lmask, land);

    // 2) qfeat = prev_h1 @ feat_in_W (49jb x 4ky) AND gates_hh = prev_h1 @ W_hh (32jb x 4ky)
    k_gemm_pair64<<<324, 128>>>(prev_h1, 512, feat_in_W, 3076, 512, 128, p_part, 49, 196,
                                prev_h1, 512, W_hh,      2048, 512, 128, p_parthh, 32);

    // 3) reduce qfeat partials
    k_reduce<<<769, 256>>>(p_part, 4, 3076, p_qfeat);

    // 4) pano object retrieval + feature-attention logits (fused)
    k_objret<<<B_ * PANO_, 256>>>(pano_obj, PANO_, land, feature, p_qfeat, nullptr, p_a, 0);

    // 5) attention-weighted feature (softmax inline)
    k_attn_feat<<<dim3(4, B_), 256>>>(feature);

    // 6) gates_ih = x @ W_ih (32jb x 5ky)
    k_gemm64<<<dim3(32, 5), 128>>>(p_x, 3140, W_ih, 2048, 3140, 640, p_part);

    // 7) LSTM pointwise
    k_lstm<<<128, 256>>>(c_0, b_lstm, out);

    // 8) ctx attention (att_in GEMM inline)
    k_ctx_attn<<<B_, 512>>>(ctx, att_in_W, cmask, out);

    // 9) att_out GEMM (64 splitK blocks) + topk2 (64 blocks), merged
    k_attout_topk<<<128, 128>>>(p_cat, att_out_W, out + OFF_CA, lmask, land, relmask, landrel);

    // 10) h_tilde = tanh(sum of att_out partials)
    k_tanh_ht<<<128, 256>>>(out);

    // 11) q2 = h_tilde @ cand_in_W (49jb x 4ky)
    k_gemm64<<<dim3(49, 4), 128>>>(out + OFF_HT, 512, cand_in_W, 3097, 512, 128, p_part);

    // 12) reduce q2 partials
    k_reduce<<<775, 256>>>(p_part, 4, 3097, p_q2);

    // 13) candidate retrieval + final logit
    k_objret<<<B_ * IMG_, 256>>>(cand_obj, IMG_, land, cand_feat, p_q2, crel, out + OFF_LOG, 1);
}

// round 14
// speedup vs baseline: 1.1441x; 1.1441x over previous
#include <cuda_runtime.h>
#include <cuda_bf16.h>
#include <math.h>
#include <stdint.h>

// Problem constants
#define B_    64
#define PANO_ 36
#define OBJ_  36
#define CFG_  16
#define LM_   8
#define IMG_  32
#define D_    300
#define H_    512
#define EMB_  64
#define ANG_  128
#define FEAT_ 2176
#define TOPN_ 3
#define M_    128
#define EPS_  1e-8f

// Output layout (flattened tuple): h_1 | c_1 | logit | h_tilde | ctx_attn
#define OFF_H1   0
#define OFF_C1   32768
#define OFF_LOG  65536
#define OFF_HT   67584
#define OFF_CA   100352

// ---------------- scratch ----------------
__device__ __align__(256) float g_x[B_*3140];       // [action_emb(64) | attn_feat(3076)]
__device__ __align__(256) float g_qfeat[B_*3076];
__device__ __align__(256) float g_cat[B_*1024];
__device__ __align__(256) float g_q2[B_*3097];
__device__ __align__(256) float g_part[800000];     // generic split-K partials (qfeat / ih / q2)
__device__ __align__(256) float g_parthh[4*64*2048];
__device__ __align__(256) float g_part2[8*64*512];  // att_in partials, then att_out partials
__device__ __align__(256) float g_pano_sim[B_*PANO_*900];
__device__ float g_a[B_*PANO_];
__device__ int   g_top1[B_*3];
__device__ float g_nb1[B_*3];
__device__ int   g_top2[B_*3];
__device__ float g_nb2[B_*3];
__device__ float g_relmask[B_*3];
__device__ float g_landrel[B_*18];

// ---------------- helpers ----------------
__device__ __forceinline__ float wred(float v) {
    #pragma unroll
    for (int o = 16; o; o >>= 1) v += __shfl_down_sync(0xffffffffu, v, o);
    return v;
}
__device__ __forceinline__ float block_reduce(float v, float* sbuf) {
    int lane = threadIdx.x & 31, w = threadIdx.x >> 5;
    v = wred(v);
    if (lane == 0) sbuf[w] = v;
    __syncthreads();
    int nw = blockDim.x >> 5;
    v = (threadIdx.x < nw) ? sbuf[threadIdx.x] : 0.f;
    if (w == 0) v = wred(v);
    return v;
}
__device__ __forceinline__ float sigmoidf_(float x) { return 1.f / (1.f + expf(-x)); }

// ---------------- FFMA split-K GEMM body (proven, float4 loads) ----------------
__device__ void gemm64_body(const float* __restrict__ A, int lda,
                            const float* __restrict__ W, int N, int K,
                            int kChunk, float* __restrict__ part,
                            int jbi, int ky) {
    __shared__ float sA[16][64];
    __shared__ float sW[16][64];
    int jb = jbi * 64;
    int k0 = ky * kChunk;
    int kEnd = min(K, k0 + kChunk);
    int tid = threadIdx.x;                 // 128 threads
    int tj = tid & 15, tb = tid >> 4;
    float acc[8][4];
    #pragma unroll
    for (int r = 0; r < 8; r++)
        #pragma unroll
        for (int c = 0; c < 4; c++) acc[r][c] = 0.f;
    int la_b = tid >> 1, la_k = (tid & 1) * 8;
    int lw_k = tid >> 3, lw_j = (tid & 7) * 8;
    bool wAligned = ((N & 3) == 0);
    for (int k = k0; k < kEnd; k += 16) {
        int kw = kEnd - k;
        if (la_k + 8 <= kw) {
            const float* ap = A + (size_t)la_b * lda + k + la_k;
            float4 v0 = *(const float4*)ap;
            float4 v1 = *(const float4*)(ap + 4);
            sA[la_k+0][la_b] = v0.x; sA[la_k+1][la_b] = v0.y;
            sA[la_k+2][la_b] = v0.z; sA[la_k+3][la_b] = v0.w;
            sA[la_k+4][la_b] = v1.x; sA[la_k+5][la_b] = v1.y;
            sA[la_k+6][la_b] = v1.z; sA[la_k+7][la_b] = v1.w;
        } else {
            #pragma unroll
            for (int e = 0; e < 8; e++) {
                int kk = la_k + e;
                sA[kk][la_b] = (kk < kw) ? A[(size_t)la_b * lda + k + kk] : 0.f;
            }
        }
        int kg = k + lw_k;
        int jg0 = jb + lw_j;
        if (lw_k < kw && wAligned && jg0 + 8 <= N) {
            const float* wp = W + (size_t)kg * N + jg0;
            float4 w0 = *(const float4*)wp;
            float4 w1 = *(const float4*)(wp + 4);
            sW[lw_k][lw_j+0] = w0.x; sW[lw_k][lw_j+1] = w0.y;
            sW[lw_k][lw_j+2] = w0.z; sW[lw_k][lw_j+3] = w0.w;
            sW[lw_k][lw_j+4] = w1.x; sW[lw_k][lw_j+5] = w1.y;
            sW[lw_k][lw_j+6] = w1.z; sW[lw_k][lw_j+7] = w1.w;
        } else {
            #pragma unroll
            for (int e = 0; e < 8; e++) {
                int jg = jg0 + e;
                sW[lw_k][lw_j+e] = (lw_k < kw && jg < N) ? W[(size_t)kg * N + jg] : 0.f;
            }
        }
        __syncthreads();
        #pragma unroll
        for (int kk = 0; kk < 16; kk++) {
            float av[8], wv[4];
            #pragma unroll
            for (int r = 0; r < 8; r++) av[r] = sA[kk][tb * 8 + r];
            #pragma unroll
            for (int c = 0; c < 4; c++) wv[c] = sW[kk][tj * 4 + c];
            #pragma unroll
            for (int r = 0; r < 8; r++)
                #pragma unroll
                for (int c = 0; c < 4; c++) acc[r][c] += av[r] * wv[c];
        }
        __syncthreads();
    }
    float* pp = part + (size_t)ky * 64 * N;
    #pragma unroll
    for (int r = 0; r < 8; r++) {
        int b = tb * 8 + r;
        #pragma unroll
        for (int c = 0; c < 4; c++) {
            int j = jb + tj * 4 + c;
            if (j < N) pp[(size_t)b * N + j] = acc[r][c];
        }
    }
}

__global__ void __launch_bounds__(128) k_gemm64(
        const float* __restrict__ A, int lda, const float* __restrict__ W,
        int N, int K, int kChunk, float* __restrict__ part) {
    gemm64_body(A, lda, W, N, K, kChunk, part, blockIdx.x, blockIdx.y);
}

__global__ void __launch_bounds__(128) k_gemm_pair64(
        const float* __restrict__ A0, int lda0, const float* __restrict__ W0,
        int N0, int K0, int kc0, float* __restrict__ p0, int njb0, int nb0,
        const float* __restrict__ A1, int lda1, const float* __restrict__ W1,
        int N1, int K1, int kc1, float* __restrict__ p1, int njb1) {
    int bid = blockIdx.x;
    if (bid < nb0) gemm64_body(A0, lda0, W0, N0, K0, kc0, p0, bid % njb0, bid / njb0);
    else {
        bid -= nb0;
        gemm64_body(A1, lda1, W1, N1, K1, kc1, p1, bid % njb1, bid / njb1);
    }
}

__global__ void k_reduce(const float* __restrict__ part, int S, int N,
                         float* __restrict__ C) {
    int idx = blockIdx.x * 256 + threadIdx.x;
    int MN = 64 * N;
    if (idx >= MN) return;
    float v = 0.f;
    for (int s = 0; s < S; s++) v += part[(size_t)s * MN + idx];
    C[idx] = v;
}

// ---------------- top-k body ----------------
__device__ void topk_body(int b,
                          const float* __restrict__ score,
                          const float* __restrict__ lmask,
                          const float* __restrict__ land,
                          const float* __restrict__ relmask_in,
                          const float* __restrict__ landrel_in,
                          int which) {
    __shared__ float sv[128];
    __shared__ int sel[3];
    int tid = threadIdx.x;
    if (tid < 128) sv[tid] = score[b * 16 + (tid >> 3)] * lmask[b * 128 + tid];
    __syncthreads();
    int* top = which ? g_top2 : g_top1;
    float* nbout = which ? g_nb2 : g_nb1;
    if (tid < 32) {
        for (int r = 0; r < 3; r++) {
            float bv = -INFINITY; int bi = 128;
            for (int m = tid; m < 128; m += 32) {
                float v = sv[m];
                if (v > bv || (v == bv && m < bi)) { bv = v; bi = m; }
            }
            #pragma unroll
            for (int off = 16; off; off >>= 1) {
                float ov = __shfl_down_sync(0xffffffffu, bv, off);
                int   oi = __shfl_down_sync(0xffffffffu, bi, off);
                if (ov > bv || (ov == bv && oi < bi)) { bv = ov; bi = oi; }
            }
            if (tid == 0) { sel[r] = bi; top[b * 3 + r] = bi; sv[bi] = -INFINITY; }
            __syncwarp();
        }
    }
    __syncthreads();
    int w = tid >> 5, lane = tid & 31;
    if (w < 3) {
        int m = sel[w];
        const float* p = land + ((size_t)b * 128 + m) * D_;
        float s = 0.f;
        for (int d = lane; d < D_; d += 32) { float v = p[d]; s += v * v; }
        s = wred(s);
        if (lane == 0) nbout[b * 3 + w] = sqrtf(s);
    }
    if (relmask_in && tid < 3)
        g_relmask[b * 3 + tid] = relmask_in[b * 128 + sel[tid]];
    if (landrel_in && tid < 18) {
        int t = tid / 6, r2 = tid % 6;
        g_landrel[b * 18 + tid] = landrel_in[((size_t)b * 128 + sel[t]) * 6 + r2];
    }
}

// ---------------- merged: action embedding (16 blocks) + topk1 (64 blocks) ----------------
__global__ void __launch_bounds__(256) k_misc1(
        const float* __restrict__ action, const float* __restrict__ embW,
        const float* __restrict__ embB,
        const float* __restrict__ s_0, const float* __restrict__ lmask,
        const float* __restrict__ land) {
    if (blockIdx.x < 16) {
        int idx = blockIdx.x * 256 + threadIdx.x;
        if (idx >= B_ * EMB_) return;
        int b = idx >> 6, e = idx & 63;
        float acc = embB[e];
        const float* a = action + b * ANG_;
        #pragma unroll 4
        for (int k = 0; k < ANG_; k++) acc += a[k] * embW[k * EMB_ + e];
        g_x[(size_t)b * 3140 + e] = tanhf(acc);
    } else {
        topk_body(blockIdx.x - 16, s_0, lmask, land, nullptr, nullptr, 0);
    }
}

// ---------------- merged: att_out GEMM (64 blocks, splitK) + topk2 (64 blocks) ----------------
__global__ void __launch_bounds__(128) k_attout_topk(
        const float* __restrict__ A, const float* __restrict__ W,
        const float* __restrict__ ctx_attn_out, const float* __restrict__ lmask,
        const float* __restrict__ land,
        const float* __restrict__ relmask_in, const float* __restrict__ landrel_in) {
    if (blockIdx.x < 64) {
        gemm64_body(A, 1024, W, 512, 1024, 128, g_part2, blockIdx.x & 7, blockIdx.x >> 3);
    } else {
        topk_body(blockIdx.x - 64, ctx_attn_out, lmask, land, relmask_in, landrel_in, 1);
    }
}

// ---------------- fused object retrieval + dot-with-query ----------------
// Landmarks register-cached; object loop software-pipelined (prefetch next
// object's loads before the current object's FMA + shuffle-reduce chain).
__global__ void __launch_bounds__(256) k_objret(
        const float* __restrict__ obj, int I,
        const float* __restrict__ land,
        const float* __restrict__ extra,      // feature or cand_feat [B,I,FEAT]
        const float* __restrict__ qbase,      // g_qfeat or g_q2
        const float* __restrict__ crel,       // [B,IMG,6] (which=1 only)
        float* __restrict__ aout, int which) {
    int bi = blockIdx.x;
    int b = bi / I;
    __shared__ float4 sl4[3][76];
    __shared__ float snb[3];
    __shared__ float ssim[OBJ_][3];
    __shared__ int sbest[3];
    __shared__ float sred[8];
    int tid = threadIdx.x;
    const int* top = which ? g_top2 : g_top1;
    const float* nb = which ? g_nb2 : g_nb1;
    if (tid < 228) {
        int t = tid / 76, i = tid % 76;
        if (i < 75)
            sl4[t][i] = ((const float4*)(land + ((size_t)b * 128 + top[b * 3 + t]) * D_))[i];
        else {
            float4 z; z.x = z.y = z.z = z.w = 0.f; sl4[t][i] = z;
        }
    }
    if (tid < 3) snb[tid] = nb[b * 3 + tid];
    __syncthreads();

    int w = tid >> 5, lane = tid & 31;
    // register-cache landmark slots (slot s -> element i = lane + 32*s; pad slot 75 = 0)
    float4 la[3][3];
    #pragma unroll
    for (int s = 0; s < 3; s++) {
        int i = lane + 32 * s;
        int ii = (i < 75) ? i : 75;
        #pragma unroll
        for (int t = 0; t < 3; t++) la[t][s] = sl4[t][ii];
    }
    bool act2 = (lane + 64) < 75;

    const float* ob = obj + (size_t)bi * OBJ_ * D_;
    // prefetch first object for this warp
    float4 c0, c1, c2;
    {
        const float4* p = (const float4*)(ob + w * D_);
        c0 = p[lane]; c1 = p[lane + 32];
        if (act2) c2 = p[lane + 64]; else { c2.x = c2.y = c2.z = c2.w = 0.f; }
    }
    for (int o = w; o < OBJ_; o += 8) {
        int on = o + 8;
        float4 n0 = c0, n1 = c1, n2 = c2;
        if (on < OBJ_) {
            const float4* p = (const float4*)(ob + on * D_);
            n0 = p[lane]; n1 = p[lane + 32];
            if (act2) n2 = p[lane + 64]; else { n2.x = n2.y = n2.z = n2.w = 0.f; }
        }
        float d0, d1, d2, nr;
        d0  = c0.x*la[0][0].x + c0.y*la[0][0].y + c0.z*la[0][0].z + c0.w*la[0][0].w;
        d1  = c0.x*la[1][0].x + c0.y*la[1][0].y + c0.z*la[1][0].z + c0.w*la[1][0].w;
        d2  = c0.x*la[2][0].x + c0.y*la[2][0].y + c0.z*la[2][0].z + c0.w*la[2][0].w;
        nr  = c0.x*c0.x + c0.y*c0.y + c0.z*c0.z + c0.w*c0.w;
        d0 += c1.x*la[0][1].x + c1.y*la[0][1].y + c1.z*la[0][1].z + c1.w*la[0][1].w;
        d1 += c1.x*la[1][1].x + c1.y*la[1][1].y + c1.z*la[1][1].z + c1.w*la[1][1].w;
        d2 += c1.x*la[2][1].x + c1.y*la[2][1].y + c1.z*la[2][1].z + c1.w*la[2][1].w;
        nr += c1.x*c1.x + c1.y*c1.y + c1.z*c1.z + c1.w*c1.w;
        d0 += c2.x*la[0][2].x + c2.y*la[0][2].y + c2.z*la[0][2].z + c2.w*la[0][2].w;
        d1 += c2.x*la[1][2].x + c2.y*la[1][2].y + c2.z*la[1][2].z + c2.w*la[1][2].w;
        d2 += c2.x*la[2][2].x + c2.y*la[2][2].y + c2.z*la[2][2].z + c2.w*la[2][2].w;
        nr += c2.x*c2.x + c2.y*c2.y + c2.z*c2.z + c2.w*c2.w;
        #pragma unroll
        for (int off = 16; off; off >>= 1) {
            d0 += __shfl_down_sync(0xffffffffu, d0, off);
            d1 += __shfl_down_sync(0xffffffffu, d1, off);
            d2 += __shfl_down_sync(0xffffffffu, d2, off);
            nr += __shfl_down_sync(0xffffffffu, nr, off);
        }
        if (lane == 0) {
            float na = sqrtf(nr);
            ssim[o][0] = d0 / fmaxf(na * snb[0], EPS_);
            ssim[o][1] = d1 / fmaxf(na * snb[1], EPS_);
            ssim[o][2] = d2 / fmaxf(na * snb[2], EPS_);
        }
        c0 = n0; c1 = n1; c2 = n2;
    }
    __syncthreads();
    if (tid < 3) {
        float bv = -INFINITY; int bo = 0;
        for (int o = 0; o < OBJ_; o++) { float v = ssim[o][tid]; if (v > bv) { bv = v; bo = o; } }
        sbest[tid] = bo;
    }
    __syncthreads();

    int qStride = which ? 3097 : 3076;
    int tStride = which ? 307  : 300;
    const float* q = qbase + (size_t)b * qStride;
    float accq = 0.f;
    const float4* f4 = (const float4*)(extra + (size_t)bi * FEAT_);
    #pragma unroll 2
    for (int i = tid; i < FEAT_/4; i += 256) {
        float4 v = f4[i];
        int d = i * 4;
        accq += v.x*q[d] + v.y*q[d+1] + v.z*q[d+2] + v.w*q[d+3];
    }
    if (tid < 225) {
        int t = tid / 75, i = tid % 75, d = i * 4;
        float4 v = ((const float4*)(ob + sbest[t] * D_))[i];
        if (!which) ((float4*)(g_pano_sim + (size_t)bi * 900 + t * 300))[i] = v;
        const float* qq = q + FEAT_ + t * tStride + d;
        accq += v.x*qq[0] + v.y*qq[1] + v.z*qq[2] + v.w*qq[3];
    }
    if (which && tid < 21) {
        int t = tid / 7, r = tid % 7;
        const float* cr = crel + (size_t)bi * 6;
        if (r < 6) {
            accq += cr[r] * g_relmask[b * 3 + t] * q[FEAT_ + t * 307 + 300 + r];
        } else {
            float dot = 0.f;
            #pragma unroll
            for (int rr = 0; rr < 6; rr++) dot += cr[rr] * g_landrel[b * 18 + t * 6 + rr];
            accq += dot * q[FEAT_ + t * 307 + 306];
        }
    }
    accq = block_reduce(accq, sred);
    if (tid == 0) aout[bi] = accq;
}

// ---------------- attention-weighted feature (softmax inline, float4) ----------------
__global__ void k_attn_feat(const float* __restrict__ feature) {
    int b = blockIdx.y;
    __shared__ float sp[PANO_];
    __shared__ float sms[2];
    if (threadIdx.x < PANO_) sp[threadIdx.x] = g_a[b * PANO_ + threadIdx.x];
    __syncthreads();
    if (threadIdx.x == 0) {
        float m = -INFINITY;
        for (int i = 0; i < PANO_; i++) m = fmaxf(m, sp[i]);
        float su = 0.f;
        for (int i = 0; i < PANO_; i++) su += expf(sp[i] - m);
        sms[0] = m; sms[1] = su;
    }
    __syncthreads();
    if (threadIdx.x < PANO_)
        sp[threadIdx.x] = expf(sp[threadIdx.x] - sms[0]) / sms[1];
    __syncthreads();
    int i = blockIdx.x * 256 + threadIdx.x;   // float4 index over 3076/4 = 769
    if (i >= 769) return;
    int d = i * 4;
    float ax = 0.f, ay = 0.f, az = 0.f, aw = 0.f;
    if (d < FEAT_) {
        const float4* f = (const float4*)(feature + (size_t)b * PANO_ * FEAT_) + i;
        #pragma unroll 4
        for (int s = 0; s < PANO_; s++) {
            float4 v = f[(size_t)s * (FEAT_/4)];
            float p = sp[s];
            ax += p*v.x; ay += p*v.y; az += p*v.z; aw += p*v.w;
        }
    } else {
        const float4* f = (const float4*)(g_pano_sim + (size_t)b * PANO_ * 900 + (d - FEAT_));
        #pragma unroll 4
        for (int s = 0; s < PANO_; s++) {
            float4 v = f[(size_t)s * 225];
            float p = sp[s];
            ax += p*v.x; ay += p*v.y; az += p*v.z; aw += p*v.w;
        }
    }
    float4 o; o.x = ax; o.y = ay; o.z = az; o.w = aw;
    *(float4*)(g_x + (size_t)b * 3140 + 64 + d) = o;
}

// ---------------- LSTM (sums ih(5) + hh(4) partials + bias) ----------------
__global__ void k_lstm(const float* __restrict__ c0,
                       const float* __restrict__ bias,
                       float* __restrict__ out) {
    int idx = blockIdx.x * 256 + threadIdx.x;
    if (idx >= B_ * H_) return;
    int b = idx >> 9, j = idx & 511;
    float g4[4];
    #pragma unroll
    for (int qg = 0; qg < 4; qg++) {
        int col = qg * 512 + j;
        float v = bias[col];
        #pragma unroll
        for (int s = 0; s < 5; s++)
            v += g_part[(size_t)s * 64 * 2048 + (size_t)b * 2048 + col];
        #pragma unroll
        for (int s = 0; s < 4; s++)
            v += g_parthh[(size_t)s * 64 * 2048 + (size_t)b * 2048 + col];
        g4[qg] = v;
    }
    float ig = sigmoidf_(g4[0]);
    float fg = sigmoidf_(g4[1]);
    float gg = tanhf(g4[2]);
    float og = sigmoidf_(g4[3]);
    float c1 = fg * c0[idx] + ig * gg;
    float h1 = og * tanhf(c1);
    out[OFF_H1 + idx] = h1;
    out[OFF_C1 + idx] = c1;
}

// ---------------- ctx attention (sums att_in 8 partials inline) ----------------
__global__ void __launch_bounds__(512) k_ctx_attn(
        const float* __restrict__ ctx,
        const unsigned char* __restrict__ cmask,
        float* __restrict__ out) {
    int b = blockIdx.x;
    int tid = threadIdx.x; // 512
    __shared__ float sqa[H_], slg[CFG_], sattn[CFG_];
    {
        float v = 0.f;
        #pragma unroll
        for (int s = 0; s < 8; s++)
            v += g_part2[(size_t)s * 64 * 512 + (size_t)b * 512 + tid];
        sqa[tid] = v;
    }
    __syncthreads();
    int w = tid >> 5, lane = tid & 31;
    const float* cb = ctx + (size_t)b * CFG_ * H_;
    {
        float acc = 0.f;
        const float* cw = cb + w * H_;
        for (int d = lane; d < H_; d += 32) acc += cw[d] * sqa[d];
        acc = wred(acc);
        if (lane == 0) slg[w] = cmask[b * CFG_ + w] ? -INFINITY : acc;
    }
    __syncthreads();
    if (tid == 0) {
        float m = -INFINITY;
        for (int s = 0; s < CFG_; s++) m = fmaxf(m, slg[s]);
        float su = 0.f;
        for (int s = 0; s < CFG_; s++) { float e = expf(slg[s] - m); sattn[s] = e; su += e; }
        float inv = 1.f / su;
        for (int s = 0; s < CFG_; s++) { sattn[s] *= inv; out[OFF_CA + b * CFG_ + s] = sattn[s]; }
    }
    __syncthreads();
    float acc = 0.f;
    #pragma unroll
    for (int s = 0; s < CFG_; s++) acc += sattn[s] * cb[(size_t)s * H_ + tid];
    g_cat[b * 1024 + tid] = acc;
    g_cat[b * 1024 + 512 + tid] = out[OFF_H1 + b * H_ + tid];
}

// ---------------- h_tilde = tanh(sum of 8 att_out partials) ----------------
__global__ void k_tanh_ht(float* __restrict__ out) {
    int idx = blockIdx.x * 256 + threadIdx.x;
    if (idx >= B_ * H_) return;
    float v = 0.f;
    #pragma unroll
    for (int s = 0; s < 8; s++) v += g_part2[(size_t)s * 64 * 512 + idx];
    out[OFF_HT + idx] = tanhf(v);
}

// ---------------- host launcher ----------------
extern "C" void kernel_launch(void* const* d_in, const int* in_sizes, int n_in,
                              void* d_out, int out_size) {
    const float* action    = (const float*)d_in[0];
    const float* feature   = (const float*)d_in[1];
    const float* cand_feat = (const float*)d_in[2];
    const float* prev_h1   = (const float*)d_in[3];
    const float* c_0       = (const float*)d_in[4];
    const float* ctx       = (const float*)d_in[5];
    const float* s_0       = (const float*)d_in[6];
    const float* land      = (const float*)d_in[7];
    const float* cand_obj  = (const float*)d_in[8];
    const float* lmask     = (const float*)d_in[9];
    const float* landrel   = (const float*)d_in[10];
    const float* relmask   = (const float*)d_in[11];
    const float* crel      = (const float*)d_in[12];
    const float* pano_obj  = (const float*)d_in[13];
    const float* embW      = (const float*)d_in[14];
    const float* embB      = (const float*)d_in[15];
    const float* W_ih      = (const float*)d_in[16];
    const float* W_hh      = (const float*)d_in[17];
    const float* b_lstm    = (const float*)d_in[18];
    const float* feat_in_W = (const float*)d_in[19];
    const float* att_in_W  = (const float*)d_in[20];
    const float* att_out_W = (const float*)d_in[21];
    const float* cand_in_W = (const float*)d_in[22];
    const unsigned char* cmask = (const unsigned char*)d_in[23];
    float* out = (float*)d_out;

    float *p_x, *p_qfeat, *p_q2, *p_part, *p_a, *p_cat, *p_parthh, *p_part2;
    cudaGetSymbolAddress((void**)&p_x,      g_x);
    cudaGetSymbolAddress((void**)&p_qfeat,  g_qfeat);
    cudaGetSymbolAddress((void**)&p_q2,     g_q2);
    cudaGetSymbolAddress((void**)&p_part,   g_part);
    cudaGetSymbolAddress((void**)&p_a,      g_a);
    cudaGetSymbolAddress((void**)&p_cat,    g_cat);
    cudaGetSymbolAddress((void**)&p_parthh, g_parthh);
    cudaGetSymbolAddress((void**)&p_part2,  g_part2);

    // 1) action embedding + topk1
    k_misc1<<<80, 256>>>(action, embW, embB, s_0, lmask, land);

    // 2) qfeat = prev_h1 @ feat_in_W (49jb x 4ky) AND gates_hh = prev_h1 @ W_hh (32jb x 4ky)
    k_gemm_pair64<<<324, 128>>>(prev_h1, 512, feat_in_W, 3076, 512, 128, p_part, 49, 196,
                                prev_h1, 512, W_hh,      2048, 512, 128, p_parthh, 32);

    // 3) reduce qfeat partials
    k_reduce<<<769, 256>>>(p_part, 4, 3076, p_qfeat);

    // 4) pano object retrieval + feature-attention logits (fused)
    k_objret<<<B_ * PANO_, 256>>>(pano_obj, PANO_, land, feature, p_qfeat, nullptr, p_a, 0);

    // 5) attention-weighted feature (softmax inline)
    k_attn_feat<<<dim3(4, B_), 256>>>(feature);

    // 6) gates_ih = x @ W_ih (32jb x 5ky)
    k_gemm64<<<dim3(32, 5), 128>>>(p_x, 3140, W_ih, 2048, 3140, 640, p_part);

    // 7) LSTM pointwise
    k_lstm<<<128, 256>>>(c_0, b_lstm, out);

    // 8) qa = h1 @ att_in_W (8jb x 8ky -> g_part2, reduced in ctx_attn)
    k_gemm64<<<dim3(8, 8), 128>>>(out + OFF_H1, 512, att_in_W, 512, 512, 64, p_part2);

    // 9) ctx attention
    k_ctx_attn<<<B_, 512>>>(ctx, cmask, out);

    // 10) att_out GEMM (64 splitK blocks) + topk2 (64 blocks), merged
    k_attout_topk<<<128, 128>>>(p_cat, att_out_W, out + OFF_CA, lmask, land, relmask, landrel);

    // 11) h_tilde = tanh(sum of att_out partials)
    k_tanh_ht<<<128, 256>>>(out);

    // 12) q2 = h_tilde @ cand_in_W (49jb x 4ky)
    k_gemm64<<<dim3(49, 4), 128>>>(out + OFF_HT, 512, cand_in_W, 3097, 512, 128, p_part);

    // 13) reduce q2 partials
    k_reduce<<<775, 256>>>(p_part, 4, 3097, p_q2);

    // 14) candidate retrieval + final logit
    k_objret<<<B_ * IMG_, 256>>>(cand_obj, IMG_, land, cand_feat, p_q2, crel, out + OFF_LOG, 1);
}

// round 15
// speedup vs baseline: 1.2698x; 1.1098x over previous
#include <cuda_runtime.h>
#include <cuda_bf16.h>
#include <math.h>
#include <stdint.h>

// Problem constants
#define B_    64
#define PANO_ 36
#define OBJ_  36
#define CFG_  16
#define LM_   8
#define IMG_  32
#define D_    300
#define H_    512
#define EMB_  64
#define ANG_  128
#define FEAT_ 2176
#define TOPN_ 3
#define M_    128
#define EPS_  1e-8f

// Output layout (flattened tuple): h_1 | c_1 | logit | h_tilde | ctx_attn
#define OFF_H1   0
#define OFF_C1   32768
#define OFF_LOG  65536
#define OFF_HT   67584
#define OFF_CA   100352

// ---------------- scratch ----------------
__device__ __align__(256) float g_x[B_*3140];       // [action_emb(64) | attn_feat(3076)]
__device__ __align__(256) float g_qfeat[B_*3076];
__device__ __align__(256) float g_cat[B_*1024];
__device__ __align__(256) float g_q2[B_*3097];
__device__ __align__(256) float g_part[8*64*2048];  // generic split-K partials (qfeat / ih / q2)
__device__ __align__(256) float g_parthh[4*64*2048];
__device__ __align__(256) float g_part2[8*64*512];  // att_in partials, then att_out partials
__device__ __align__(256) float g_pano_sim[B_*PANO_*900];
__device__ float g_a[B_*PANO_];
__device__ int   g_top1[B_*3];
__device__ float g_nb1[B_*3];
__device__ int   g_top2[B_*3];
__device__ float g_nb2[B_*3];
__device__ float g_relmask[B_*3];
__device__ float g_landrel[B_*18];

// ---------------- helpers ----------------
__device__ __forceinline__ float wred(float v) {
    #pragma unroll
    for (int o = 16; o; o >>= 1) v += __shfl_down_sync(0xffffffffu, v, o);
    return v;
}
__device__ __forceinline__ float block_reduce(float v, float* sbuf) {
    int lane = threadIdx.x & 31, w = threadIdx.x >> 5;
    v = wred(v);
    if (lane == 0) sbuf[w] = v;
    __syncthreads();
    int nw = blockDim.x >> 5;
    v = (threadIdx.x < nw) ? sbuf[threadIdx.x] : 0.f;
    if (w == 0) v = wred(v);
    return v;
}
__device__ __forceinline__ float sigmoidf_(float x) { return 1.f / (1.f + expf(-x)); }

// ---------------- FFMA split-K GEMM body (proven, float4 loads) ----------------
__device__ void gemm64_body(const float* __restrict__ A, int lda,
                            const float* __restrict__ W, int N, int K,
                            int kChunk, float* __restrict__ part,
                            int jbi, int ky) {
    __shared__ float sA[16][64];
    __shared__ float sW[16][64];
    int jb = jbi * 64;
    int k0 = ky * kChunk;
    int kEnd = min(K, k0 + kChunk);
    int tid = threadIdx.x;                 // 128 threads
    int tj = tid & 15, tb = tid >> 4;
    float acc[8][4];
    #pragma unroll
    for (int r = 0; r < 8; r++)
        #pragma unroll
        for (int c = 0; c < 4; c++) acc[r][c] = 0.f;
    int la_b = tid >> 1, la_k = (tid & 1) * 8;
    int lw_k = tid >> 3, lw_j = (tid & 7) * 8;
    bool wAligned = ((N & 3) == 0);
    for (int k = k0; k < kEnd; k += 16) {
        int kw = kEnd - k;
        if (la_k + 8 <= kw) {
            const float* ap = A + (size_t)la_b * lda + k + la_k;
            float4 v0 = *(const float4*)ap;
            float4 v1 = *(const float4*)(ap + 4);
            sA[la_k+0][la_b] = v0.x; sA[la_k+1][la_b] = v0.y;
            sA[la_k+2][la_b] = v0.z; sA[la_k+3][la_b] = v0.w;
            sA[la_k+4][la_b] = v1.x; sA[la_k+5][la_b] = v1.y;
            sA[la_k+6][la_b] = v1.z; sA[la_k+7][la_b] = v1.w;
        } else {
            #pragma unroll
            for (int e = 0; e < 8; e++) {
                int kk = la_k + e;
                sA[kk][la_b] = (kk < kw) ? A[(size_t)la_b * lda + k + kk] : 0.f;
            }
        }
        int kg = k + lw_k;
        int jg0 = jb + lw_j;
        if (lw_k < kw && wAligned && jg0 + 8 <= N) {
            const float* wp = W + (size_t)kg * N + jg0;
            float4 w0 = *(const float4*)wp;
            float4 w1 = *(const float4*)(wp + 4);
            sW[lw_k][lw_j+0] = w0.x; sW[lw_k][lw_j+1] = w0.y;
            sW[lw_k][lw_j+2] = w0.z; sW[lw_k][lw_j+3] = w0.w;
            sW[lw_k][lw_j+4] = w1.x; sW[lw_k][lw_j+5] = w1.y;
            sW[lw_k][lw_j+6] = w1.z; sW[lw_k][lw_j+7] = w1.w;
        } else {
            #pragma unroll
            for (int e = 0; e < 8; e++) {
                int jg = jg0 + e;
                sW[lw_k][lw_j+e] = (lw_k < kw && jg < N) ? W[(size_t)kg * N + jg] : 0.f;
            }
        }
        __syncthreads();
        #pragma unroll
        for (int kk = 0; kk < 16; kk++) {
            float av[8], wv[4];
            #pragma unroll
            for (int r = 0; r < 8; r++) av[r] = sA[kk][tb * 8 + r];
            #pragma unroll
            for (int c = 0; c < 4; c++) wv[c] = sW[kk][tj * 4 + c];
            #pragma unroll
            for (int r = 0; r < 8; r++)
                #pragma unroll
                for (int c = 0; c < 4; c++) acc[r][c] += av[r] * wv[c];
        }
        __syncthreads();
    }
    float* pp = part + (size_t)ky * 64 * N;
    #pragma unroll
    for (int r = 0; r < 8; r++) {
        int b = tb * 8 + r;
        #pragma unroll
        for (int c = 0; c < 4; c++) {
            int j = jb + tj * 4 + c;
            if (j < N) pp[(size_t)b * N + j] = acc[r][c];
        }
    }
}

__global__ void __launch_bounds__(128) k_gemm64(
        const float* __restrict__ A, int lda, const float* __restrict__ W,
        int N, int K, int kChunk, float* __restrict__ part) {
    gemm64_body(A, lda, W, N, K, kChunk, part, blockIdx.x, blockIdx.y);
}

__global__ void __launch_bounds__(128) k_gemm_pair64(
        const float* __restrict__ A0, int lda0, const float* __restrict__ W0,
        int N0, int K0, int kc0, float* __restrict__ p0, int njb0, int nb0,
        const float* __restrict__ A1, int lda1, const float* __restrict__ W1,
        int N1, int K1, int kc1, float* __restrict__ p1, int njb1) {
    int bid = blockIdx.x;
    if (bid < nb0) gemm64_body(A0, lda0, W0, N0, K0, kc0, p0, bid % njb0, bid / njb0);
    else {
        bid -= nb0;
        gemm64_body(A1, lda1, W1, N1, K1, kc1, p1, bid % njb1, bid / njb1);
    }
}

__global__ void k_reduce(const float* __restrict__ part, int S, int N,
                         float* __restrict__ C) {
    int idx = blockIdx.x * 256 + threadIdx.x;
    int MN = 64 * N;
    if (idx >= MN) return;
    float v = 0.f;
    for (int s = 0; s < S; s++) v += part[(size_t)s * MN + idx];
    C[idx] = v;
}

// ---------------- top-k body ----------------
__device__ void topk_body(int b,
                          const float* __restrict__ score,
                          const float* __restrict__ lmask,
                          const float* __restrict__ land,
                          const float* __restrict__ relmask_in,
                          const float* __restrict__ landrel_in,
                          int which) {
    __shared__ float sv[128];
    __shared__ int sel[3];
    int tid = threadIdx.x;
    if (tid < 128) sv[tid] = score[b * 16 + (tid >> 3)] * lmask[b * 128 + tid];
    __syncthreads();
    int* top = which ? g_top2 : g_top1;
    float* nbout = which ? g_nb2 : g_nb1;
    if (tid < 32) {
        for (int r = 0; r < 3; r++) {
            float bv = -INFINITY; int bi = 128;
            for (int m = tid; m < 128; m += 32) {
                float v = sv[m];
                if (v > bv || (v == bv && m < bi)) { bv = v; bi = m; }
            }
            #pragma unroll
            for (int off = 16; off; off >>= 1) {
                float ov = __shfl_down_sync(0xffffffffu, bv, off);
                int   oi = __shfl_down_sync(0xffffffffu, bi, off);
                if (ov > bv || (ov == bv && oi < bi)) { bv = ov; bi = oi; }
            }
            if (tid == 0) { sel[r] = bi; top[b * 3 + r] = bi; sv[bi] = -INFINITY; }
            __syncwarp();
        }
    }
    __syncthreads();
    int w = tid >> 5, lane = tid & 31;
    if (w < 3) {
        int m = sel[w];
        const float* p = land + ((size_t)b * 128 + m) * D_;
        float s = 0.f;
        for (int d = lane; d < D_; d += 32) { float v = p[d]; s += v * v; }
        s = wred(s);
        if (lane == 0) nbout[b * 3 + w] = sqrtf(s);
    }
    if (relmask_in && tid < 3)
        g_relmask[b * 3 + tid] = relmask_in[b * 128 + sel[tid]];
    if (landrel_in && tid < 18) {
        int t = tid / 6, r2 = tid % 6;
        g_landrel[b * 18 + tid] = landrel_in[((size_t)b * 128 + sel[t]) * 6 + r2];
    }
}

// ---------------- merged: action embedding (16 blocks) + topk1 (64 blocks) ----------------
__global__ void __launch_bounds__(256) k_misc1(
        const float* __restrict__ action, const float* __restrict__ embW,
        const float* __restrict__ embB,
        const float* __restrict__ s_0, const float* __restrict__ lmask,
        const float* __restrict__ land) {
    if (blockIdx.x < 16) {
        int idx = blockIdx.x * 256 + threadIdx.x;
        if (idx >= B_ * EMB_) return;
        int b = idx >> 6, e = idx & 63;
        float acc = embB[e];
        const float* a = action + b * ANG_;
        #pragma unroll 4
        for (int k = 0; k < ANG_; k++) acc += a[k] * embW[k * EMB_ + e];
        g_x[(size_t)b * 3140 + e] = tanhf(acc);
    } else {
        topk_body(blockIdx.x - 16, s_0, lmask, land, nullptr, nullptr, 0);
    }
}

// ---------------- merged: att_out GEMM (64 blocks, splitK) + topk2 (64 blocks) ----------------
__global__ void __launch_bounds__(128) k_attout_topk(
        const float* __restrict__ A, const float* __restrict__ W,
        const float* __restrict__ ctx_attn_out, const float* __restrict__ lmask,
        const float* __restrict__ land,
        const float* __restrict__ relmask_in, const float* __restrict__ landrel_in) {
    if (blockIdx.x < 64) {
        gemm64_body(A, 1024, W, 512, 1024, 128, g_part2, blockIdx.x & 7, blockIdx.x >> 3);
    } else {
        topk_body(blockIdx.x - 64, ctx_attn_out, lmask, land, relmask_in, landrel_in, 1);
    }
}

// ---------------- fused object retrieval + dot-with-query ----------------
// Landmark slots 0/1 register-cached, slot 2 from smem (only 11/32 lanes live);
// object loop software-pipelined. __launch_bounds__(256,4) targets 4 blocks/SM.
__global__ void __launch_bounds__(256, 4) k_objret(
        const float* __restrict__ obj, int I,
        const float* __restrict__ land,
        const float* __restrict__ extra,      // feature or cand_feat [B,I,FEAT]
        const float* __restrict__ qbase,      // g_qfeat or g_q2
        const float* __restrict__ crel,       // [B,IMG,6] (which=1 only)
        float* __restrict__ aout, int which) {
    int bi = blockIdx.x;
    int b = bi / I;
    __shared__ float4 sl4[3][76];
    __shared__ float snb[3];
    __shared__ float ssim[OBJ_][3];
    __shared__ int sbest[3];
    __shared__ float sred[8];
    int tid = threadIdx.x;
    const int* top = which ? g_top2 : g_top1;
    const float* nb = which ? g_nb2 : g_nb1;
    if (tid < 228) {
        int t = tid / 76, i = tid % 76;
        if (i < 75)
            sl4[t][i] = ((const float4*)(land + ((size_t)b * 128 + top[b * 3 + t]) * D_))[i];
        else {
            float4 z; z.x = z.y = z.z = z.w = 0.f; sl4[t][i] = z;
        }
    }
    if (tid < 3) snb[tid] = nb[b * 3 + tid];
    __syncthreads();

    int w = tid >> 5, lane = tid & 31;
    // register-cache landmark slots 0,1 only (slot 2 read from smem in-loop)
    float4 la[3][2];
    #pragma unroll
    for (int s = 0; s < 2; s++)
        #pragma unroll
        for (int t = 0; t < 3; t++) la[t][s] = sl4[t][lane + 32 * s];
    bool act2 = (lane + 64) < 75;
    int i2 = act2 ? (lane + 64) : 75;     // padded zero slot

    const float* ob = obj + (size_t)bi * OBJ_ * D_;
    // prefetch first object for this warp
    float4 c0, c1, c2;
    {
        const float4* p = (const float4*)(ob + w * D_);
        c0 = p[lane]; c1 = p[lane + 32];
        if (act2) c2 = p[lane + 64]; else { c2.x = c2.y = c2.z = c2.w = 0.f; }
    }
    for (int o = w; o < OBJ_; o += 8) {
        int on = o + 8;
        float4 n0 = c0, n1 = c1, n2 = c2;
        if (on < OBJ_) {
            const float4* p = (const float4*)(ob + on * D_);
            n0 = p[lane]; n1 = p[lane + 32];
            if (act2) n2 = p[lane + 64]; else { n2.x = n2.y = n2.z = n2.w = 0.f; }
        }
        float d0, d1, d2, nr;
        d0  = c0.x*la[0][0].x + c0.y*la[0][0].y + c0.z*la[0][0].z + c0.w*la[0][0].w;
        d1  = c0.x*la[1][0].x + c0.y*la[1][0].y + c0.z*la[1][0].z + c0.w*la[1][0].w;
        d2  = c0.x*la[2][0].x + c0.y*la[2][0].y + c0.z*la[2][0].z + c0.w*la[2][0].w;
        nr  = c0.x*c0.x + c0.y*c0.y + c0.z*c0.z + c0.w*c0.w;
        d0 += c1.x*la[0][1].x + c1.y*la[0][1].y + c1.z*la[0][1].z + c1.w*la[0][1].w;
        d1 += c1.x*la[1][1].x + c1.y*la[1][1].y + c1.z*la[1][1].z + c1.w*la[1][1].w;
        d2 += c1.x*la[2][1].x + c1.y*la[2][1].y + c1.z*la[2][1].z + c1.w*la[2][1].w;
        nr += c1.x*c1.x + c1.y*c1.y + c1.z*c1.z + c1.w*c1.w;
        {
            float4 l0 = sl4[0][i2], l1 = sl4[1][i2], l2 = sl4[2][i2];
            d0 += c2.x*l0.x + c2.y*l0.y + c2.z*l0.z + c2.w*l0.w;
            d1 += c2.x*l1.x + c2.y*l1.y + c2.z*l1.z + c2.w*l1.w;
            d2 += c2.x*l2.x + c2.y*l2.y + c2.z*l2.z + c2.w*l2.w;
            nr += c2.x*c2.x + c2.y*c2.y + c2.z*c2.z + c2.w*c2.w;
        }
        #pragma unroll
        for (int off = 16; off; off >>= 1) {
            d0 += __shfl_down_sync(0xffffffffu, d0, off);
            d1 += __shfl_down_sync(0xffffffffu, d1, off);
            d2 += __shfl_down_sync(0xffffffffu, d2, off);
            nr += __shfl_down_sync(0xffffffffu, nr, off);
        }
        if (lane == 0) {
            float na = sqrtf(nr);
            ssim[o][0] = d0 / fmaxf(na * snb[0], EPS_);
            ssim[o][1] = d1 / fmaxf(na * snb[1], EPS_);
            ssim[o][2] = d2 / fmaxf(na * snb[2], EPS_);
        }
        c0 = n0; c1 = n1; c2 = n2;
    }
    __syncthreads();
    if (tid < 3) {
        float bv = -INFINITY; int bo = 0;
        for (int o = 0; o < OBJ_; o++) { float v = ssim[o][tid]; if (v > bv) { bv = v; bo = o; } }
        sbest[tid] = bo;
    }
    __syncthreads();

    int qStride = which ? 3097 : 3076;
    int tStride = which ? 307  : 300;
    const float* q = qbase + (size_t)b * qStride;
    float accq = 0.f;
    const float4* f4 = (const float4*)(extra + (size_t)bi * FEAT_);
    #pragma unroll 2
    for (int i = tid; i < FEAT_/4; i += 256) {
        float4 v = f4[i];
        int d = i * 4;
        accq += v.x*q[d] + v.y*q[d+1] + v.z*q[d+2] + v.w*q[d+3];
    }
    if (tid < 225) {
        int t = tid / 75, i = tid % 75, d = i * 4;
        float4 v = ((const float4*)(ob + sbest[t] * D_))[i];
        if (!which) ((float4*)(g_pano_sim + (size_t)bi * 900 + t * 300))[i] = v;
        const float* qq = q + FEAT_ + t * tStride + d;
        accq += v.x*qq[0] + v.y*qq[1] + v.z*qq[2] + v.w*qq[3];
    }
    if (which && tid < 21) {
        int t = tid / 7, r = tid % 7;
        const float* cr = crel + (size_t)bi * 6;
        if (r < 6) {
            accq += cr[r] * g_relmask[b * 3 + t] * q[FEAT_ + t * 307 + 300 + r];
        } else {
            float dot = 0.f;
            #pragma unroll
            for (int rr = 0; rr < 6; rr++) dot += cr[rr] * g_landrel[b * 18 + t * 6 + rr];
            accq += dot * q[FEAT_ + t * 307 + 306];
        }
    }
    accq = block_reduce(accq, sred);
    if (tid == 0) aout[bi] = accq;
}

// ---------------- attention-weighted feature (softmax inline, float4) ----------------
__global__ void k_attn_feat(const float* __restrict__ feature) {
    int b = blockIdx.y;
    __shared__ float sp[PANO_];
    __shared__ float sms[2];
    if (threadIdx.x < PANO_) sp[threadIdx.x] = g_a[b * PANO_ + threadIdx.x];
    __syncthreads();
    if (threadIdx.x == 0) {
        float m = -INFINITY;
        for (int i = 0; i < PANO_; i++) m = fmaxf(m, sp[i]);
        float su = 0.f;
        for (int i = 0; i < PANO_; i++) su += expf(sp[i] - m);
        sms[0] = m; sms[1] = su;
    }
    __syncthreads();
    if (threadIdx.x < PANO_)
        sp[threadIdx.x] = expf(sp[threadIdx.x] - sms[0]) / sms[1];
    __syncthreads();
    int i = blockIdx.x * 256 + threadIdx.x;   // float4 index over 3076/4 = 769
    if (i >= 769) return;
    int d = i * 4;
    float ax = 0.f, ay = 0.f, az = 0.f, aw = 0.f;
    float bx = 0.f, by = 0.f, bz = 0.f, bw = 0.f;
    if (d < FEAT_) {
        const float4* f = (const float4*)(feature + (size_t)b * PANO_ * FEAT_) + i;
        #pragma unroll 6
        for (int s = 0; s < PANO_; s += 2) {
            float4 v0 = f[(size_t)s * (FEAT_/4)];
            float4 v1 = f[(size_t)(s+1) * (FEAT_/4)];
            float p0 = sp[s], p1 = sp[s+1];
            ax += p0*v0.x; ay += p0*v0.y; az += p0*v0.z; aw += p0*v0.w;
            bx += p1*v1.x; by += p1*v1.y; bz += p1*v1.z; bw += p1*v1.w;
        }
    } else {
        const float4* f = (const float4*)(g_pano_sim + (size_t)b * PANO_ * 900 + (d - FEAT_));
        #pragma unroll 6
        for (int s = 0; s < PANO_; s += 2) {
            float4 v0 = f[(size_t)s * 225];
            float4 v1 = f[(size_t)(s+1) * 225];
            float p0 = sp[s], p1 = sp[s+1];
            ax += p0*v0.x; ay += p0*v0.y; az += p0*v0.z; aw += p0*v0.w;
            bx += p1*v1.x; by += p1*v1.y; bz += p1*v1.z; bw += p1*v1.w;
        }
    }
    float4 o; o.x = ax + bx; o.y = ay + by; o.z = az + bz; o.w = aw + bw;
    *(float4*)(g_x + (size_t)b * 3140 + 64 + d) = o;
}

// ---------------- LSTM (sums ih(8) + hh(4) partials + bias) ----------------
__global__ void k_lstm(const float* __restrict__ c0,
                       const float* __restrict__ bias,
                       float* __restrict__ out) {
    int idx = blockIdx.x * 256 + threadIdx.x;
    if (idx >= B_ * H_) return;
    int b = idx >> 9, j = idx & 511;
    float g4[4];
    #pragma unroll
    for (int qg = 0; qg < 4; qg++) {
        int col = qg * 512 + j;
        float v = bias[col];
        #pragma unroll
        for (int s = 0; s < 8; s++)
            v += g_part[(size_t)s * 64 * 2048 + (size_t)b * 2048 + col];
        #pragma unroll
        for (int s = 0; s < 4; s++)
            v += g_parthh[(size_t)s * 64 * 2048 + (size_t)b * 2048 + col];
        g4[qg] = v;
    }
    float ig = sigmoidf_(g4[0]);
    float fg = sigmoidf_(g4[1]);
    float gg = tanhf(g4[2]);
    float og = sigmoidf_(g4[3]);
    float c1 = fg * c0[idx] + ig * gg;
    float h1 = og * tanhf(c1);
    out[OFF_H1 + idx] = h1;
    out[OFF_C1 + idx] = c1;
}

// ---------------- ctx attention (sums att_in 8 partials inline) ----------------
__global__ void __launch_bounds__(512) k_ctx_attn(
        const float* __restrict__ ctx,
        const unsigned char* __restrict__ cmask,
        float* __restrict__ out) {
    int b = blockIdx.x;
    int tid = threadIdx.x; // 512
    __shared__ float sqa[H_], slg[CFG_], sattn[CFG_];
    {
        float v = 0.f;
        #pragma unroll
        for (int s = 0; s < 8; s++)
            v += g_part2[(size_t)s * 64 * 512 + (size_t)b * 512 + tid];
        sqa[tid] = v;
    }
    __syncthreads();
    int w = tid >> 5, lane = tid & 31;
    const float* cb = ctx + (size_t)b * CFG_ * H_;
    {
        float acc = 0.f;
        const float* cw = cb + w * H_;
        for (int d = lane; d < H_; d += 32) acc += cw[d] * sqa[d];
        acc = wred(acc);
        if (lane == 0) slg[w] = cmask[b * CFG_ + w] ? -INFINITY : acc;
    }
    __syncthreads();
    if (tid == 0) {
        float m = -INFINITY;
        for (int s = 0; s < CFG_; s++) m = fmaxf(m, slg[s]);
        float su = 0.f;
        for (int s = 0; s < CFG_; s++) { float e = expf(slg[s] - m); sattn[s] = e; su += e; }
        float inv = 1.f / su;
        for (int s = 0; s < CFG_; s++) { sattn[s] *= inv; out[OFF_CA + b * CFG_ + s] = sattn[s]; }
    }
    __syncthreads();
    float acc = 0.f;
    #pragma unroll
    for (int s = 0; s < CFG_; s++) acc += sattn[s] * cb[(size_t)s * H_ + tid];
    g_cat[b * 1024 + tid] = acc;
    g_cat[b * 1024 + 512 + tid] = out[OFF_H1 + b * H_ + tid];
}

// ---------------- h_tilde = tanh(sum of 8 att_out partials) ----------------
__global__ void k_tanh_ht(float* __restrict__ out) {
    int idx = blockIdx.x * 256 + threadIdx.x;
    if (idx >= B_ * H_) return;
    float v = 0.f;
    #pragma unroll
    for (int s = 0; s < 8; s++) v += g_part2[(size_t)s * 64 * 512 + idx];
    out[OFF_HT + idx] = tanhf(v);
}

// ---------------- host launcher ----------------
extern "C" void kernel_launch(void* const* d_in, const int* in_sizes, int n_in,
                              void* d_out, int out_size) {
    const float* action    = (const float*)d_in[0];
    const float* feature   = (const float*)d_in[1];
    const float* cand_feat = (const float*)d_in[2];
    const float* prev_h1   = (const float*)d_in[3];
    const float* c_0       = (const float*)d_in[4];
    const float* ctx       = (const float*)d_in[5];
    const float* s_0       = (const float*)d_in[6];
    const float* land      = (const float*)d_in[7];
    const float* cand_obj  = (const float*)d_in[8];
    const float* lmask     = (const float*)d_in[9];
    const float* landrel   = (const float*)d_in[10];
    const float* relmask   = (const float*)d_in[11];
    const float* crel      = (const float*)d_in[12];
    const float* pano_obj  = (const float*)d_in[13];
    const float* embW      = (const float*)d_in[14];
    const float* embB      = (const float*)d_in[15];
    const float* W_ih      = (const float*)d_in[16];
    const float* W_hh      = (const float*)d_in[17];
    const float* b_lstm    = (const float*)d_in[18];
    const float* feat_in_W = (const float*)d_in[19];
    const float* att_in_W  = (const float*)d_in[20];
    const float* att_out_W = (const float*)d_in[21];
    const float* cand_in_W = (const float*)d_in[22];
    const unsigned char* cmask = (const unsigned char*)d_in[23];
    float* out = (float*)d_out;

    float *p_x, *p_qfeat, *p_q2, *p_part, *p_a, *p_cat, *p_parthh, *p_part2;
    cudaGetSymbolAddress((void**)&p_x,      g_x);
    cudaGetSymbolAddress((void**)&p_qfeat,  g_qfeat);
    cudaGetSymbolAddress((void**)&p_q2,     g_q2);
    cudaGetSymbolAddress((void**)&p_part,   g_part);
    cudaGetSymbolAddress((void**)&p_a,      g_a);
    cudaGetSymbolAddress((void**)&p_cat,    g_cat);
    cudaGetSymbolAddress((void**)&p_parthh, g_parthh);
    cudaGetSymbolAddress((void**)&p_part2,  g_part2);

    // 1) action embedding + topk1
    k_misc1<<<80, 256>>>(action, embW, embB, s_0, lmask, land);

    // 2) qfeat = prev_h1 @ feat_in_W (49jb x 4ky) AND gates_hh = prev_h1 @ W_hh (32jb x 4ky)
    k_gemm_pair64<<<324, 128>>>(prev_h1, 512, feat_in_W, 3076, 512, 128, p_part, 49, 196,
                                prev_h1, 512, W_hh,      2048, 512, 128, p_parthh, 32);

    // 3) reduce qfeat partials
    k_reduce<<<769, 256>>>(p_part, 4, 3076, p_qfeat);

    // 4) pano object retrieval + feature-attention logits (fused)
    k_objret<<<B_ * PANO_, 256>>>(pano_obj, PANO_, land, feature, p_qfeat, nullptr, p_a, 0);

    // 5) attention-weighted feature (softmax inline)
    k_attn_feat<<<dim3(4, B_), 256>>>(feature);

    // 6) gates_ih = x @ W_ih (32jb x 8ky = 256 blocks)
    k_gemm64<<<dim3(32, 8), 128>>>(p_x, 3140, W_ih, 2048, 3140, 400, p_part);

    // 7) LSTM pointwise (8 ih + 4 hh partials)
    k_lstm<<<128, 256>>>(c_0, b_lstm, out);

    // 8) qa = h1 @ att_in_W (8jb x 8ky -> g_part2, reduced in ctx_attn)
    k_gemm64<<<dim3(8, 8), 128>>>(out + OFF_H1, 512, att_in_W, 512, 512, 64, p_part2);

    // 9) ctx attention
    k_ctx_attn<<<B_, 512>>>(ctx, cmask, out);

    // 10) att_out GEMM (64 splitK blocks) + topk2 (64 blocks), merged
    k_attout_topk<<<128, 128>>>(p_cat, att_out_W, out + OFF_CA, lmask, land, relmask, landrel);

    // 11) h_tilde = tanh(sum of att_out partials)
    k_tanh_ht<<<128, 256>>>(out);

    // 12) q2 = h_tilde @ cand_in_W (49jb x 4ky)
    k_gemm64<<<dim3(49, 4), 128>>>(out + OFF_HT, 512, cand_in_W, 3097, 512, 128, p_part);

    // 13) reduce q2 partials
    k_reduce<<<775, 256>>>(p_part, 4, 3097, p_q2);

    // 14) candidate retrieval + final logit
    k_objret<<<B_ * IMG_, 256>>>(cand_obj, IMG_, land, cand_feat, p_q2, crel, out + OFF_LOG, 1);
}